// round 13
// baseline (speedup 1.0000x reference)
#include <cuda_runtime.h>
#include <cuda_fp16.h>
#include <cstdint>
#include <cstddef>

// ============================================================================
// RNNEncoder: h_t = relu(x_t@Wx^T + h_{t-1}@Wh^T + b), 35 steps (fp16 mma.sync).
// Persistent decomposition with unified ticket pool:
//   conv tickets: x fp32->fp16, 32 row-blocks per timestep (1120 total)
//   z tickets   : z_t = x_t@Wx^T + b, 256 tiles per timestep (8960 total)
//   h chain     : h_t = relu(z_t + h_{t-1}@Wh^T), 256 fixed owner CTAs
// Grid = 296 CTAs (2/SM). Conv work overlaps GEMM (complementary resources).
// ============================================================================

#define B_ROWS   4096
#define U_DIM    1024
#define T_STEPS  35
#define K_FULL   2048
#define XSTRIDE  (T_STEPS * U_DIM)
#define NCH      16                  // chunks per tile-GEMM (K=1024)
#define ROWB     144                 // 64 halves = 128B + 16B pad
#define A_TILE   (128 * ROWB)
#define W_TILE   (128 * ROWB)
#define STAGE    (A_TILE + W_TILE)   // 36864
#define PIPE     3
#define SMEM_TOT (PIPE * STAGE)      // 110592 (x2 CTAs = 221184)
#define NTILES   256
#define NCTA     296

#define CONV_PER_T 32
#define ITEMS_PER_T (CONV_PER_T + NTILES)        // 288
#define TOTAL_ITEMS (T_STEPS * ITEMS_PER_T)      // 10080

// g_sync layout: [0]=ticket, [1+t]=zdone, [40+t]=hbar, [128 + t*32 + rb]=convdone
#define SY_TICKET 0
#define SY_ZDONE(t)   (1 + (t))
#define SY_HBAR(t)    (40 + (t))
#define SY_CONV(t,rb) (128 + (t) * CONV_PER_T + (rb))
#define SY_SIZE 1280

// ---------------------------------------------------------------------------
__device__ __half    g_x16[(size_t)B_ROWS * T_STEPS * U_DIM];
__device__ __half    g_w16[(size_t)U_DIM * K_FULL];
__device__ __half    g_h16[2][(size_t)B_ROWS * U_DIM];
__device__ float     g_z[(size_t)T_STEPS * B_ROWS * U_DIM];
__device__ unsigned  g_sync[SY_SIZE];

// ---------------------------------------------------------------------------
__device__ __forceinline__ uint32_t smem_u32(const void* p) {
    uint32_t a;
    asm("{ .reg .u64 t; cvta.to.shared.u64 t, %1; cvt.u32.u64 %0, t; }" : "=r"(a) : "l"(p));
    return a;
}
#define CP16(s, g) asm volatile("cp.async.cg.shared.global [%0], [%1], 16;\n" :: "r"(s), "l"(g) : "memory")
#define CP_COMMIT() asm volatile("cp.async.commit_group;\n" ::: "memory")
#define CP_WAIT(n)  asm volatile("cp.async.wait_group %0;\n" :: "n"(n) : "memory")

__device__ __forceinline__ void ldsm_x4(uint32_t& r0, uint32_t& r1, uint32_t& r2, uint32_t& r3,
                                        uint32_t addr) {
    asm volatile("ldmatrix.sync.aligned.m8n8.x4.shared.b16 {%0,%1,%2,%3}, [%4];"
                 : "=r"(r0), "=r"(r1), "=r"(r2), "=r"(r3) : "r"(addr));
}
__device__ __forceinline__ void mma_f16(float* c, const uint32_t* a, const uint32_t* b) {
    asm volatile(
        "mma.sync.aligned.m16n8k16.row.col.f32.f16.f16.f32 "
        "{%0,%1,%2,%3}, {%4,%5,%6,%7}, {%8,%9}, {%0,%1,%2,%3};"
        : "+f"(c[0]), "+f"(c[1]), "+f"(c[2]), "+f"(c[3])
        : "r"(a[0]), "r"(a[1]), "r"(a[2]), "r"(a[3]), "r"(b[0]), "r"(b[1]));
}

// ---------------------------------------------------------------------------
__device__ __forceinline__ void load_chunk16(
    uint32_t stage, int chunk, const __half* __restrict__ aBase, size_t aStride,
    const __half* __restrict__ wBase, int colBase, int tid)
{
    const int k0 = chunk * 64;
    #pragma unroll
    for (int it = 0; it < 8; it++) {
        const int i = tid + it * 128;
        const int r = i >> 3, c = i & 7;
        const uint32_t so = (uint32_t)(r * ROWB + c * 16);
        CP16(stage + so, aBase + (size_t)r * aStride + k0 + c * 8);
    }
    #pragma unroll
    for (int it = 0; it < 8; it++) {
        const int i = tid + it * 128;
        const int r = i >> 3, c = i & 7;
        const uint32_t so = (uint32_t)(r * ROWB + c * 16);
        CP16(stage + A_TILE + so, wBase + (size_t)(colBase + r) * K_FULL + k0 + c * 8);
    }
}

// 128x128 tile GEMM over K=1024 (16 chunks), accumulating into acc.
__device__ __forceinline__ void tile_gemm16(
    uint32_t sb, const __half* __restrict__ aBase, size_t aStride,
    const __half* __restrict__ wBase, int colBase,
    int tid, int lane, int warpM, int warpN, float acc[4][8][4])
{
    __syncthreads();   // protect smem stages from the previous tile's readers
    #pragma unroll
    for (int p = 0; p < PIPE - 1; p++) {
        load_chunk16(sb + p * STAGE, p, aBase, aStride, wBase, colBase, tid);
        CP_COMMIT();
    }
    const uint32_t aRowOff = (uint32_t)(lane & 15) * ROWB + (uint32_t)(lane >> 4) * 16;
    const uint32_t bRowOff = (uint32_t)((lane & 7) + ((lane >> 4) << 3)) * ROWB
                           + (uint32_t)((lane >> 3) & 1) * 16;
    for (int c = 0; c < NCH; c++) {
        CP_WAIT(1);
        __syncthreads();
        if (c + 2 < NCH)
            load_chunk16(sb + ((c + 2) % PIPE) * STAGE, c + 2, aBase, aStride, wBase, colBase, tid);
        CP_COMMIT();

        const uint32_t st = sb + (c % PIPE) * STAGE;
        uint32_t aF[2][4][4];
        #pragma unroll
        for (int mt = 0; mt < 4; mt++) {
            const uint32_t ao = (uint32_t)(warpM + mt * 16) * ROWB + aRowOff;
            ldsm_x4(aF[0][mt][0], aF[0][mt][1], aF[0][mt][2], aF[0][mt][3], st + ao);
        }
        #pragma unroll
        for (int s = 0; s < 4; s++) {
            const uint32_t ks = s * 32;
            uint32_t bH[4][4];
            #pragma unroll
            for (int q = 0; q < 4; q++) {
                const uint32_t bo = (uint32_t)(warpN + q * 16) * ROWB + bRowOff + ks;
                ldsm_x4(bH[q][0], bH[q][1], bH[q][2], bH[q][3], st + A_TILE + bo);
            }
            if (s < 3) {
                #pragma unroll
                for (int mt = 0; mt < 4; mt++) {
                    const uint32_t ao = (uint32_t)(warpM + mt * 16) * ROWB + aRowOff + ks + 32;
                    ldsm_x4(aF[(s + 1) & 1][mt][0], aF[(s + 1) & 1][mt][1],
                            aF[(s + 1) & 1][mt][2], aF[(s + 1) & 1][mt][3], st + ao);
                }
            }
            #pragma unroll
            for (int mt = 0; mt < 4; mt++)
                #pragma unroll
                for (int q = 0; q < 4; q++) {
                    mma_f16(acc[mt][2*q],   aF[s & 1][mt], &bH[q][0]);
                    mma_f16(acc[mt][2*q+1], aF[s & 1][mt], &bH[q][2]);
                }
        }
    }
}

// ---------------------------------------------------------------------------
// conv ticket: convert x fp32 -> fp16 for timestep t, row-block rb (128 rows)
__device__ __forceinline__ void do_conv_tile(
    int t, int rb, const float* __restrict__ x32, __half* __restrict__ x16, int tid)
{
    const size_t rowStart = (size_t)rb * 128;
    const float4* src = (const float4*)(x32 + rowStart * XSTRIDE + (size_t)t * U_DIM);
    __half2*      dst = (__half2*)(x16 + rowStart * XSTRIDE + (size_t)t * U_DIM);
    // 128 rows x 256 float4/row; coalesced: idx = it*128 + tid
    #pragma unroll 4
    for (int it = 0; it < 256; it++) {
        const int idx = it * 128 + tid;
        const int r = idx >> 8, c = idx & 255;
        const size_t so = (size_t)r * (XSTRIDE / 4) + c;
        const size_t do2 = (size_t)r * (XSTRIDE / 2) + c * 2;
        const float4 v = src[so];
        dst[do2]     = __floats2half2_rn(v.x, v.y);
        dst[do2 + 1] = __floats2half2_rn(v.z, v.w);
    }
    __syncthreads();
    if (tid == 0) { __threadfence(); atomicExch(&g_sync[SY_CONV(t, rb)], 1u); }
}

// z ticket: z(t,tile) = x_t @ Wx^T + b (fp32 store, no relu)
__device__ __forceinline__ void do_z_tile(
    uint32_t sb, int t, int tile,
    const __half* __restrict__ x16, const __half* __restrict__ w16,
    const float* __restrict__ bias, float* __restrict__ z,
    int tid, int lane, int warpM, int warpN)
{
    const int rowBase = (tile >> 3) * 128;
    const int colBase = (tile & 7) * 128;

    // wait for this row-block's x conversion (short: conv ticket issued earlier)
    if (tid == 0) {
        while (*(volatile unsigned*)&g_sync[SY_CONV(t, tile >> 3)] == 0u) __nanosleep(200);
    }
    __syncthreads();
    __threadfence();   // acquire x16 writes

    float acc[4][8][4];
    #pragma unroll
    for (int i = 0; i < 4; i++)
        #pragma unroll
        for (int j = 0; j < 8; j++)
            #pragma unroll
            for (int q = 0; q < 4; q++) acc[i][j][q] = 0.0f;

    tile_gemm16(sb, x16 + (size_t)t * U_DIM + (size_t)rowBase * XSTRIDE, XSTRIDE,
                w16, colBase, tid, lane, warpM, warpN, acc);

    float* zt = z + (size_t)t * B_ROWS * U_DIM;
    #pragma unroll
    for (int mt = 0; mt < 4; mt++) {
        const int r0 = rowBase + warpM + mt * 16 + (lane >> 2);
        #pragma unroll
        for (int nt = 0; nt < 8; nt++) {
            const int col = colBase + warpN + nt * 8 + (lane & 3) * 2;
            const float2 bv = *(const float2*)(bias + col);
            *(float2*)(zt + (size_t)r0 * U_DIM + col) =
                make_float2(acc[mt][nt][0] + bv.x, acc[mt][nt][1] + bv.y);
            *(float2*)(zt + (size_t)(r0 + 8) * U_DIM + col) =
                make_float2(acc[mt][nt][2] + bv.x, acc[mt][nt][3] + bv.y);
        }
    }
    __syncthreads();
    if (tid == 0) { __threadfence(); atomicAdd(&g_sync[SY_ZDONE(t)], 1u); }
}

// dispatch one pool ticket
__device__ __forceinline__ void do_ticket(
    uint32_t sb, unsigned w,
    const float* __restrict__ x32, __half* __restrict__ x16,
    const __half* __restrict__ w16, const float* __restrict__ bias,
    float* __restrict__ z, int tid, int lane, int warpM, int warpN)
{
    const int t = (int)(w / ITEMS_PER_T);
    const int r = (int)(w % ITEMS_PER_T);
    if (r < CONV_PER_T) do_conv_tile(t, r, x32, x16, tid);
    else                do_z_tile(sb, t, r - CONV_PER_T, x16, w16, bias, z,
                                  tid, lane, warpM, warpN);
}

// ---------------------------------------------------------------------------
__global__ __launch_bounds__(128, 2)
void rnn_persist(const float* __restrict__ x32, __half* __restrict__ x16,
                 const __half* __restrict__ w16,
                 __half* __restrict__ h16, const float* __restrict__ bias,
                 float* __restrict__ z, float* __restrict__ out)
{
    extern __shared__ char smem[];
    const uint32_t sb = smem_u32(smem);
    const int tid  = threadIdx.x;
    const int lane = tid & 31;
    const int warp = tid >> 5;
    const int warpM = (warp & 1) * 64;
    const int warpN = (warp >> 1) * 64;
    const size_t HSZ = (size_t)B_ROWS * U_DIM;

    __shared__ unsigned sh_work;

    // -------- pure pool workers (CTAs 256..295) --------
    if (blockIdx.x >= NTILES) {
        while (true) {
            if (tid == 0) sh_work = atomicAdd(&g_sync[SY_TICKET], 1u);
            __syncthreads();
            const unsigned w = sh_work;
            __syncthreads();
            if (w >= TOTAL_ITEMS) return;
            do_ticket(sb, w, x32, x16, w16, bias, z, tid, lane, warpM, warpN);
        }
    }

    // -------- fixed h-owner CTAs (0..255) --------
    const int myTile  = blockIdx.x;
    const int rowBase = (myTile >> 3) * 128;
    const int colBase = (myTile & 7) * 128;
    bool pooldead = false;

    for (int t = 0; t < T_STEPS; t++) {
        // wait for z(t) complete and h(t-1) barrier; fill wait with pool work
        while (true) {
            if (tid == 0) {
                const bool ready =
                    (*(volatile unsigned*)&g_sync[SY_ZDONE(t)] >= NTILES) &&
                    (t == 0 || *(volatile unsigned*)&g_sync[SY_HBAR(t - 1)] >= NTILES);
                if (ready)          sh_work = 0xFFFFFFFFu;
                else if (!pooldead) sh_work = atomicAdd(&g_sync[SY_TICKET], 1u);
                else                sh_work = 0xFFFFFFFEu;
            }
            __syncthreads();
            const unsigned w = sh_work;
            __syncthreads();
            if (w == 0xFFFFFFFFu) break;
            if (w < TOTAL_ITEMS) {
                do_ticket(sb, w, x32, x16, w16, bias, z, tid, lane, warpM, warpN);
            } else {
                pooldead = true;
                if (tid == 0) __nanosleep(500);
                __syncthreads();
            }
        }
        __threadfence();   // acquire: z(t) and h(t-1) writes visible

        const __half* hprev = h16 + (size_t)(t & 1) * HSZ;
        __half*       hout  = h16 + (size_t)((t + 1) & 1) * HSZ;
        const float*  zt    = z + (size_t)t * B_ROWS * U_DIM;

        if (t == 0) {
            // h0 = relu(z0) elementwise
            #pragma unroll
            for (int mt = 0; mt < 4; mt++) {
                const int r0 = rowBase + warpM + mt * 16 + (lane >> 2);
                #pragma unroll
                for (int nt = 0; nt < 8; nt++) {
                    const int col = colBase + warpN + nt * 8 + (lane & 3) * 2;
                    const float2 a = *(const float2*)(zt + (size_t)r0 * U_DIM + col);
                    const float2 b2 = *(const float2*)(zt + (size_t)(r0 + 8) * U_DIM + col);
                    *(__half2*)(hout + (size_t)r0 * U_DIM + col) =
                        __floats2half2_rn(a.x > 0.f ? a.x : 0.f, a.y > 0.f ? a.y : 0.f);
                    *(__half2*)(hout + (size_t)(r0 + 8) * U_DIM + col) =
                        __floats2half2_rn(b2.x > 0.f ? b2.x : 0.f, b2.y > 0.f ? b2.y : 0.f);
                }
            }
        } else {
            float acc[4][8][4];
            #pragma unroll
            for (int mt = 0; mt < 4; mt++) {
                const int r0 = rowBase + warpM + mt * 16 + (lane >> 2);
                #pragma unroll
                for (int nt = 0; nt < 8; nt++) {
                    const int col = colBase + warpN + nt * 8 + (lane & 3) * 2;
                    const float2 a = *(const float2*)(zt + (size_t)r0 * U_DIM + col);
                    const float2 b2 = *(const float2*)(zt + (size_t)(r0 + 8) * U_DIM + col);
                    acc[mt][nt][0] = a.x;  acc[mt][nt][1] = a.y;
                    acc[mt][nt][2] = b2.x; acc[mt][nt][3] = b2.y;
                }
            }
            tile_gemm16(sb, hprev + (size_t)rowBase * U_DIM, U_DIM,
                        w16 + U_DIM, colBase, tid, lane, warpM, warpN, acc);

            const int writeF = (t == T_STEPS - 1);
            #pragma unroll
            for (int mt = 0; mt < 4; mt++) {
                const int r0 = rowBase + warpM + mt * 16 + (lane >> 2);
                #pragma unroll
                for (int nt = 0; nt < 8; nt++) {
                    const int col = colBase + warpN + nt * 8 + (lane & 3) * 2;
                    float v0 = acc[mt][nt][0]; v0 = v0 > 0.f ? v0 : 0.f;
                    float v1 = acc[mt][nt][1]; v1 = v1 > 0.f ? v1 : 0.f;
                    float v2 = acc[mt][nt][2]; v2 = v2 > 0.f ? v2 : 0.f;
                    float v3 = acc[mt][nt][3]; v3 = v3 > 0.f ? v3 : 0.f;
                    const size_t o0 = (size_t)r0 * U_DIM + col;
                    const size_t o1 = o0 + 8 * U_DIM;
                    if (writeF) {
                        *(float2*)(out + o0) = make_float2(v0, v1);
                        *(float2*)(out + o1) = make_float2(v2, v3);
                    } else {
                        *(__half2*)(hout + o0) = __floats2half2_rn(v0, v1);
                        *(__half2*)(hout + o1) = __floats2half2_rn(v2, v3);
                    }
                }
            }
        }
        __syncthreads();
        if (tid == 0) { __threadfence(); atomicAdd(&g_sync[SY_HBAR(t)], 1u); }
    }
}

// ---------------------------------------------------------------------------
__global__ void conv_f16_kernel(const float4* __restrict__ src,
                                __half2* __restrict__ dst, size_t n4)
{
    size_t i = (size_t)blockIdx.x * blockDim.x + threadIdx.x;
    if (i >= n4) return;
    float4 v = src[i];
    dst[2*i]   = __floats2half2_rn(v.x, v.y);
    dst[2*i+1] = __floats2half2_rn(v.z, v.w);
}

// ---------------------------------------------------------------------------
extern "C" void kernel_launch(void* const* d_in, const int* in_sizes, int n_in,
                              void* d_out, int out_size)
{
    const float* x = (const float*)d_in[0];
    const float* W = (const float*)d_in[1];
    const float* b = (const float*)d_in[2];
    float* out = (float*)d_out;

    __half *x16, *w16, *h16;
    float *z;
    unsigned* syncp;
    cudaGetSymbolAddress((void**)&x16, g_x16);
    cudaGetSymbolAddress((void**)&w16, g_w16);
    cudaGetSymbolAddress((void**)&h16, g_h16);
    cudaGetSymbolAddress((void**)&z,   g_z);
    cudaGetSymbolAddress((void**)&syncp, g_sync);

    static bool attr_set = false;
    if (!attr_set) {
        cudaFuncSetAttribute(rnn_persist, cudaFuncAttributeMaxDynamicSharedMemorySize, SMEM_TOT);
        attr_set = true;
    }

    // reset sync state (graph-replay safe)
    cudaMemsetAsync(syncp, 0, SY_SIZE * sizeof(unsigned));

    // W fp32 -> fp16 (small; stays a pre-kernel)
    {
        size_t nW4 = (size_t)U_DIM * K_FULL / 4;
        conv_f16_kernel<<<(unsigned)((nW4 + 255) / 256), 256>>>(
            (const float4*)W, (__half2*)w16, nW4);
    }

    rnn_persist<<<NCTA, 128, SMEM_TOT>>>(x, x16, w16, h16, b, z, out);
}

// round 14
// speedup vs baseline: 1.1777x; 1.1777x over previous
#include <cuda_runtime.h>
#include <cuda_fp16.h>
#include <cstdint>
#include <cstddef>

// ============================================================================
// RNNEncoder: h_t = relu(x_t@Wx^T + h_{t-1}@Wh^T + b), 35 steps (fp16 mma.sync).
// Persistent decomposition (R11 structure, proven):
//   z tickets: z_t = x_t@Wx^T + b  -- 256 tiles/timestep, global ordered pool.
//              A operand read DIRECTLY from fp32 x (cp.async fp32 + cvt in
//              fragment load) -- no x16 conversion pass at all.
//   h chain  : h_t = relu(z_t + h_{t-1}@Wh^T) -- 256 fixed owner CTAs, fp16.
// Grid = 296 CTAs (2/SM): 256 h-owners (fill waits with z work) + 40 z-workers.
// ============================================================================

#define B_ROWS   4096
#define U_DIM    1024
#define T_STEPS  35
#define K_FULL   2048
#define XSTRIDE  (T_STEPS * U_DIM)
#define NCH      16                  // chunks per tile-GEMM (K=1024)
#define ROWB     144                 // 64 halves = 128B + 16B pad
#define ROWB32   272                 // 64 floats = 256B + 16B pad
#define A_TILE   (128 * ROWB)        // fp16 A tile (h path)
#define W_TILE   (128 * ROWB)
#define A32_TILE (128 * ROWB32)      // 34816, fp32 A tile (z path)
#define STAGE_H  (A_TILE + W_TILE)   // 36864
#define STAGE_Z  (A32_TILE + W_TILE) // 53248
#define PIPE_H   3
#define SMEM_TOT (PIPE_H * STAGE_H)  // 110592 (>= 2*STAGE_Z = 106496)
#define NTILES   256
#define NCTA     296
#define ZTILES   (T_STEPS * NTILES)  // 8960

// g_sync: [0]=ticket, [1+t]=zdone[t], [64+t]=hbar[t]
#define SY_SIZE 128

// ---------------------------------------------------------------------------
__device__ __half    g_w16[(size_t)U_DIM * K_FULL];
__device__ __half    g_h16[2][(size_t)B_ROWS * U_DIM];
__device__ float     g_z[(size_t)T_STEPS * B_ROWS * U_DIM];
__device__ unsigned  g_sync[SY_SIZE];

// ---------------------------------------------------------------------------
__device__ __forceinline__ uint32_t smem_u32(const void* p) {
    uint32_t a;
    asm("{ .reg .u64 t; cvta.to.shared.u64 t, %1; cvt.u32.u64 %0, t; }" : "=r"(a) : "l"(p));
    return a;
}
#define CP16(s, g) asm volatile("cp.async.cg.shared.global [%0], [%1], 16;\n" :: "r"(s), "l"(g) : "memory")
#define CP_COMMIT() asm volatile("cp.async.commit_group;\n" ::: "memory")
#define CP_WAIT(n)  asm volatile("cp.async.wait_group %0;\n" :: "n"(n) : "memory")

__device__ __forceinline__ void ldsm_x4(uint32_t& r0, uint32_t& r1, uint32_t& r2, uint32_t& r3,
                                        uint32_t addr) {
    asm volatile("ldmatrix.sync.aligned.m8n8.x4.shared.b16 {%0,%1,%2,%3}, [%4];"
                 : "=r"(r0), "=r"(r1), "=r"(r2), "=r"(r3) : "r"(addr));
}
__device__ __forceinline__ void mma_f16(float* c, const uint32_t* a, const uint32_t* b) {
    asm volatile(
        "mma.sync.aligned.m16n8k16.row.col.f32.f16.f16.f32 "
        "{%0,%1,%2,%3}, {%4,%5,%6,%7}, {%8,%9}, {%0,%1,%2,%3};"
        : "+f"(c[0]), "+f"(c[1]), "+f"(c[2]), "+f"(c[3])
        : "r"(a[0]), "r"(a[1]), "r"(a[2]), "r"(a[3]), "r"(b[0]), "r"(b[1]));
}
__device__ __forceinline__ uint32_t packh2(float x, float y) {
    __half2 h = __floats2half2_rn(x, y);
    return *reinterpret_cast<uint32_t*>(&h);
}

// ===========================================================================
// h-path: fp16 A + fp16 W, PIPE=3 (identical to R11)
// ===========================================================================
__device__ __forceinline__ void load_chunk_h(
    uint32_t stage, int chunk, const __half* __restrict__ aBase, size_t aStride,
    const __half* __restrict__ wBase, int colBase, int tid)
{
    const int k0 = chunk * 64;
    #pragma unroll
    for (int it = 0; it < 8; it++) {
        const int i = tid + it * 128;
        const int r = i >> 3, c = i & 7;
        CP16(stage + (uint32_t)(r * ROWB + c * 16), aBase + (size_t)r * aStride + k0 + c * 8);
    }
    #pragma unroll
    for (int it = 0; it < 8; it++) {
        const int i = tid + it * 128;
        const int r = i >> 3, c = i & 7;
        CP16(stage + A_TILE + (uint32_t)(r * ROWB + c * 16),
             wBase + (size_t)(colBase + r) * K_FULL + k0 + c * 8);
    }
}

__device__ __forceinline__ void tile_gemm_h(
    uint32_t sb, const __half* __restrict__ aBase, size_t aStride,
    const __half* __restrict__ wBase, int colBase,
    int tid, int lane, int warpM, int warpN, float acc[4][8][4])
{
    __syncthreads();
    #pragma unroll
    for (int p = 0; p < PIPE_H - 1; p++) {
        load_chunk_h(sb + p * STAGE_H, p, aBase, aStride, wBase, colBase, tid);
        CP_COMMIT();
    }
    const uint32_t aRowOff = (uint32_t)(lane & 15) * ROWB + (uint32_t)(lane >> 4) * 16;
    const uint32_t bRowOff = (uint32_t)((lane & 7) + ((lane >> 4) << 3)) * ROWB
                           + (uint32_t)((lane >> 3) & 1) * 16;
    for (int c = 0; c < NCH; c++) {
        CP_WAIT(1);
        __syncthreads();
        if (c + 2 < NCH)
            load_chunk_h(sb + ((c + 2) % PIPE_H) * STAGE_H, c + 2, aBase, aStride, wBase, colBase, tid);
        CP_COMMIT();

        const uint32_t st = sb + (c % PIPE_H) * STAGE_H;
        uint32_t aF[2][4][4];
        #pragma unroll
        for (int mt = 0; mt < 4; mt++) {
            const uint32_t ao = (uint32_t)(warpM + mt * 16) * ROWB + aRowOff;
            ldsm_x4(aF[0][mt][0], aF[0][mt][1], aF[0][mt][2], aF[0][mt][3], st + ao);
        }
        #pragma unroll
        for (int s = 0; s < 4; s++) {
            const uint32_t ks = s * 32;
            uint32_t bH[4][4];
            #pragma unroll
            for (int q = 0; q < 4; q++) {
                const uint32_t bo = (uint32_t)(warpN + q * 16) * ROWB + bRowOff + ks;
                ldsm_x4(bH[q][0], bH[q][1], bH[q][2], bH[q][3], st + A_TILE + bo);
            }
            if (s < 3) {
                #pragma unroll
                for (int mt = 0; mt < 4; mt++) {
                    const uint32_t ao = (uint32_t)(warpM + mt * 16) * ROWB + aRowOff + ks + 32;
                    ldsm_x4(aF[(s + 1) & 1][mt][0], aF[(s + 1) & 1][mt][1],
                            aF[(s + 1) & 1][mt][2], aF[(s + 1) & 1][mt][3], st + ao);
                }
            }
            #pragma unroll
            for (int mt = 0; mt < 4; mt++)
                #pragma unroll
                for (int q = 0; q < 4; q++) {
                    mma_f16(acc[mt][2*q],   aF[s & 1][mt], &bH[q][0]);
                    mma_f16(acc[mt][2*q+1], aF[s & 1][mt], &bH[q][2]);
                }
        }
    }
}

// ===========================================================================
// z-path: fp32 A (direct from x) + fp16 W, PIPE=2
// ===========================================================================
__device__ __forceinline__ void load_chunk_z(
    uint32_t stage, int chunk, const float* __restrict__ aBase,
    const __half* __restrict__ wBase, int colBase, int tid)
{
    const int k0 = chunk * 64;
    // A fp32: 128 rows x 16 x 16B = 2048 copies -> 16 iters
    #pragma unroll
    for (int it = 0; it < 16; it++) {
        const int i = tid + it * 128;
        const int r = i >> 4, c = i & 15;
        CP16(stage + (uint32_t)(r * ROWB32 + c * 16),
             aBase + (size_t)r * XSTRIDE + k0 + c * 4);
    }
    // W fp16: 128 rows x 8 x 16B
    #pragma unroll
    for (int it = 0; it < 8; it++) {
        const int i = tid + it * 128;
        const int r = i >> 3, c = i & 7;
        CP16(stage + A32_TILE + (uint32_t)(r * ROWB + c * 16),
             wBase + (size_t)(colBase + r) * K_FULL + k0 + c * 8);
    }
}

__device__ __forceinline__ void tile_gemm_z(
    uint32_t sb, char* smemBytes, const float* __restrict__ aBase,
    const __half* __restrict__ wBase, int colBase,
    int tid, int lane, int warpM, int warpN, float acc[4][8][4])
{
    __syncthreads();
    load_chunk_z(sb + 0 * STAGE_Z, 0, aBase, wBase, colBase, tid); CP_COMMIT();
    load_chunk_z(sb + 1 * STAGE_Z, 1, aBase, wBase, colBase, tid); CP_COMMIT();

    const int fr = lane >> 2;            // fragment row 0..7
    const int fc = (lane & 3) * 2;       // fragment col pair base
    const uint32_t bRowOff = (uint32_t)((lane & 7) + ((lane >> 4) << 3)) * ROWB
                           + (uint32_t)((lane >> 3) & 1) * 16;

    for (int c = 0; c < NCH; c++) {
        CP_WAIT(1);
        __syncthreads();
        const int bufOff = (c & 1) * STAGE_Z;
        const uint32_t stW = sb + bufOff + A32_TILE;
        const char* stA = smemBytes + bufOff;

        #pragma unroll
        for (int s = 0; s < 4; s++) {
            const uint32_t ks = s * 32;
            // A fragments: fp32 smem -> cvt -> fp16 pairs (ldmatrix-equivalent)
            uint32_t aF[4][4];
            #pragma unroll
            for (int mt = 0; mt < 4; mt++) {
                const char* ap = stA + (warpM + mt * 16 + fr) * ROWB32 + (s * 16 + fc) * 4;
                const float2 v0 = *(const float2*)(ap);
                const float2 v1 = *(const float2*)(ap + 8 * ROWB32);
                const float2 v2 = *(const float2*)(ap + 32);
                const float2 v3 = *(const float2*)(ap + 8 * ROWB32 + 32);
                aF[mt][0] = packh2(v0.x, v0.y);
                aF[mt][1] = packh2(v1.x, v1.y);
                aF[mt][2] = packh2(v2.x, v2.y);
                aF[mt][3] = packh2(v3.x, v3.y);
            }
            uint32_t bH[4][4];
            #pragma unroll
            for (int q = 0; q < 4; q++) {
                const uint32_t bo = (uint32_t)(warpN + q * 16) * ROWB + bRowOff + ks;
                ldsm_x4(bH[q][0], bH[q][1], bH[q][2], bH[q][3], stW + bo);
            }
            #pragma unroll
            for (int mt = 0; mt < 4; mt++)
                #pragma unroll
                for (int q = 0; q < 4; q++) {
                    mma_f16(acc[mt][2*q],   aF[mt], &bH[q][0]);
                    mma_f16(acc[mt][2*q+1], aF[mt], &bH[q][2]);
                }
        }
        __syncthreads();   // all reads of this buffer done before refill
        if (c + 2 < NCH)
            load_chunk_z(sb + bufOff, c + 2, aBase, wBase, colBase, tid);
        CP_COMMIT();
    }
}

// ---------------------------------------------------------------------------
// z ticket: z(t,tile) = x_t @ Wx^T + b (fp32 store, no relu)
__device__ __forceinline__ void do_z_tile(
    uint32_t sb, char* smemBytes, unsigned zi,
    const float* __restrict__ x32, const __half* __restrict__ w16,
    const float* __restrict__ bias, float* __restrict__ z,
    int tid, int lane, int warpM, int warpN)
{
    const int t    = (int)(zi >> 8);
    const int tile = (int)(zi & 255);
    const int rowBase = (tile >> 3) * 128;
    const int colBase = (tile & 7) * 128;

    float acc[4][8][4];
    #pragma unroll
    for (int i = 0; i < 4; i++)
        #pragma unroll
        for (int j = 0; j < 8; j++)
            #pragma unroll
            for (int q = 0; q < 4; q++) acc[i][j][q] = 0.0f;

    tile_gemm_z(sb, smemBytes, x32 + (size_t)t * U_DIM + (size_t)rowBase * XSTRIDE,
                w16, colBase, tid, lane, warpM, warpN, acc);

    float* zt = z + (size_t)t * B_ROWS * U_DIM;
    #pragma unroll
    for (int mt = 0; mt < 4; mt++) {
        const int r0 = rowBase + warpM + mt * 16 + (lane >> 2);
        #pragma unroll
        for (int nt = 0; nt < 8; nt++) {
            const int col = colBase + warpN + nt * 8 + (lane & 3) * 2;
            const float2 bv = *(const float2*)(bias + col);
            *(float2*)(zt + (size_t)r0 * U_DIM + col) =
                make_float2(acc[mt][nt][0] + bv.x, acc[mt][nt][1] + bv.y);
            *(float2*)(zt + (size_t)(r0 + 8) * U_DIM + col) =
                make_float2(acc[mt][nt][2] + bv.x, acc[mt][nt][3] + bv.y);
        }
    }
    __syncthreads();
    if (tid == 0) { __threadfence(); atomicAdd(&g_sync[1 + t], 1u); }
}

// ---------------------------------------------------------------------------
__global__ __launch_bounds__(128, 2)
void rnn_persist(const float* __restrict__ x32, const __half* __restrict__ w16,
                 __half* __restrict__ h16, const float* __restrict__ bias,
                 float* __restrict__ z, float* __restrict__ out)
{
    extern __shared__ char smem[];
    const uint32_t sb = smem_u32(smem);
    const int tid  = threadIdx.x;
    const int lane = tid & 31;
    const int warp = tid >> 5;
    const int warpM = (warp & 1) * 64;
    const int warpN = (warp >> 1) * 64;
    const size_t HSZ = (size_t)B_ROWS * U_DIM;

    __shared__ unsigned sh_work;

    // -------- pure z-workers (CTAs 256..295) --------
    if (blockIdx.x >= NTILES) {
        while (true) {
            if (tid == 0) sh_work = atomicAdd(&g_sync[0], 1u);
            __syncthreads();
            const unsigned zi = sh_work;
            __syncthreads();
            if (zi >= ZTILES) return;
            do_z_tile(sb, smem, zi, x32, w16, bias, z, tid, lane, warpM, warpN);
        }
    }

    // -------- fixed h-owner CTAs (0..255) --------
    const int myTile  = blockIdx.x;
    const int rowBase = (myTile >> 3) * 128;
    const int colBase = (myTile & 7) * 128;
    bool pooldead = false;

    for (int t = 0; t < T_STEPS; t++) {
        // wait for z(t) complete and h(t-1) barrier; fill wait with z work
        while (true) {
            if (tid == 0) {
                const bool ready =
                    (*(volatile unsigned*)&g_sync[1 + t] >= NTILES) &&
                    (t == 0 || *(volatile unsigned*)&g_sync[64 + (t - 1)] >= NTILES);
                if (ready)          sh_work = 0xFFFFFFFFu;
                else if (!pooldead) sh_work = atomicAdd(&g_sync[0], 1u);
                else                sh_work = 0xFFFFFFFEu;
            }
            __syncthreads();
            const unsigned w = sh_work;
            __syncthreads();
            if (w == 0xFFFFFFFFu) break;
            if (w < ZTILES) {
                do_z_tile(sb, smem, w, x32, w16, bias, z, tid, lane, warpM, warpN);
            } else {
                pooldead = true;
                if (tid == 0) __nanosleep(500);
                __syncthreads();
            }
        }
        __threadfence();   // acquire: z(t) and h(t-1) writes visible

        const __half* hprev = h16 + (size_t)(t & 1) * HSZ;
        __half*       hout  = h16 + (size_t)((t + 1) & 1) * HSZ;
        const float*  zt    = z + (size_t)t * B_ROWS * U_DIM;

        if (t == 0) {
            // h0 = relu(z0) elementwise
            #pragma unroll
            for (int mt = 0; mt < 4; mt++) {
                const int r0 = rowBase + warpM + mt * 16 + (lane >> 2);
                #pragma unroll
                for (int nt = 0; nt < 8; nt++) {
                    const int col = colBase + warpN + nt * 8 + (lane & 3) * 2;
                    const float2 a  = *(const float2*)(zt + (size_t)r0 * U_DIM + col);
                    const float2 b2 = *(const float2*)(zt + (size_t)(r0 + 8) * U_DIM + col);
                    *(__half2*)(hout + (size_t)r0 * U_DIM + col) =
                        __floats2half2_rn(a.x > 0.f ? a.x : 0.f, a.y > 0.f ? a.y : 0.f);
                    *(__half2*)(hout + (size_t)(r0 + 8) * U_DIM + col) =
                        __floats2half2_rn(b2.x > 0.f ? b2.x : 0.f, b2.y > 0.f ? b2.y : 0.f);
                }
            }
        } else {
            float acc[4][8][4];
            #pragma unroll
            for (int mt = 0; mt < 4; mt++) {
                const int r0 = rowBase + warpM + mt * 16 + (lane >> 2);
                #pragma unroll
                for (int nt = 0; nt < 8; nt++) {
                    const int col = colBase + warpN + nt * 8 + (lane & 3) * 2;
                    const float2 a  = *(const float2*)(zt + (size_t)r0 * U_DIM + col);
                    const float2 b2 = *(const float2*)(zt + (size_t)(r0 + 8) * U_DIM + col);
                    acc[mt][nt][0] = a.x;  acc[mt][nt][1] = a.y;
                    acc[mt][nt][2] = b2.x; acc[mt][nt][3] = b2.y;
                }
            }
            tile_gemm_h(sb, hprev + (size_t)rowBase * U_DIM, U_DIM,
                        w16 + U_DIM, colBase, tid, lane, warpM, warpN, acc);

            const int writeF = (t == T_STEPS - 1);
            #pragma unroll
            for (int mt = 0; mt < 4; mt++) {
                const int r0 = rowBase + warpM + mt * 16 + (lane >> 2);
                #pragma unroll
                for (int nt = 0; nt < 8; nt++) {
                    const int col = colBase + warpN + nt * 8 + (lane & 3) * 2;
                    float v0 = acc[mt][nt][0]; v0 = v0 > 0.f ? v0 : 0.f;
                    float v1 = acc[mt][nt][1]; v1 = v1 > 0.f ? v1 : 0.f;
                    float v2 = acc[mt][nt][2]; v2 = v2 > 0.f ? v2 : 0.f;
                    float v3 = acc[mt][nt][3]; v3 = v3 > 0.f ? v3 : 0.f;
                    const size_t o0 = (size_t)r0 * U_DIM + col;
                    const size_t o1 = o0 + 8 * U_DIM;
                    if (writeF) {
                        *(float2*)(out + o0) = make_float2(v0, v1);
                        *(float2*)(out + o1) = make_float2(v2, v3);
                    } else {
                        *(__half2*)(hout + o0) = __floats2half2_rn(v0, v1);
                        *(__half2*)(hout + o1) = __floats2half2_rn(v2, v3);
                    }
                }
            }
        }
        __syncthreads();
        if (tid == 0) { __threadfence(); atomicAdd(&g_sync[64 + t], 1u); }
    }
}

// ---------------------------------------------------------------------------
__global__ void conv_f16_kernel(const float4* __restrict__ src,
                                __half2* __restrict__ dst, size_t n4)
{
    size_t i = (size_t)blockIdx.x * blockDim.x + threadIdx.x;
    if (i >= n4) return;
    float4 v = src[i];
    dst[2*i]   = __floats2half2_rn(v.x, v.y);
    dst[2*i+1] = __floats2half2_rn(v.z, v.w);
}

// ---------------------------------------------------------------------------
extern "C" void kernel_launch(void* const* d_in, const int* in_sizes, int n_in,
                              void* d_out, int out_size)
{
    const float* x = (const float*)d_in[0];
    const float* W = (const float*)d_in[1];
    const float* b = (const float*)d_in[2];
    float* out = (float*)d_out;

    __half *w16, *h16;
    float *z;
    unsigned* syncp;
    cudaGetSymbolAddress((void**)&w16, g_w16);
    cudaGetSymbolAddress((void**)&h16, g_h16);
    cudaGetSymbolAddress((void**)&z,   g_z);
    cudaGetSymbolAddress((void**)&syncp, g_sync);

    static bool attr_set = false;
    if (!attr_set) {
        cudaFuncSetAttribute(rnn_persist, cudaFuncAttributeMaxDynamicSharedMemorySize, SMEM_TOT);
        attr_set = true;
    }

    // reset sync state (graph-replay safe)
    cudaMemsetAsync(syncp, 0, SY_SIZE * sizeof(unsigned));

    // W fp32 -> fp16 (12MB, ~6us; stays a pre-kernel)
    {
        size_t nW4 = (size_t)U_DIM * K_FULL / 4;
        conv_f16_kernel<<<(unsigned)((nW4 + 255) / 256), 256>>>(
            (const float4*)W, (__half2*)w16, nW4);
    }

    rnn_persist<<<NCTA, 128, SMEM_TOT>>>(x, w16, h16, b, z, out);
}